// round 11
// baseline (speedup 1.0000x reference)
#include <cuda_runtime.h>
#include <cstdint>

// Spiking1DLIFLayer: B=128, C=512, T=1024  (row=(b,c), serial recurrence over T)
//   mem = (mem*beta + x[t]) - spk_prev*Vth[c] ;  spk = mem > Vth[c]
//
// R11: SMSP SPREADING. R3-R10 used single-warp CTAs -> every warp has wid=0 ->
// all warps land on SMSP 0 (wid%4 scheduler mapping); measured issue 22.7%
// avg == ~91% on that one scheduler, saturating it while 3 idle. This round:
// 128-thread blocks = 4 INDEPENDENT warp-local pipelines (one per SMSP), each
// identical to R10's winner: cp.async.cg double-buffered input, GROUP=4
// write-through 512B bursts (keeps L2 clean at exit -> no replay-boundary
// dirty-drain tax), __syncwarp-only synchronization.
// Numerics bit-identical to reference (rel_err 0.0 in R1-R10).

#define Bdim 128
#define Cdim 512
#define Tdim 1024
#define NT    128                // 4 warps per block
#define WARPS 4
#define RPW   32                 // rows per warp (lane == row)
#define TS    32                 // time-tile (floats)
#define F4    (TS / 4)           // 8 float4 per row per tile
#define PITCH (F4 + 1)           // 9 -> conflict-free input access
#define NBUF  2
#define NTILES (Tdim / TS)       // 32
#define GROUP 4                  // tiles per write burst (512B/row)
#define ACC_PITCH (GROUP * F4 + 1)  // 33

// per-warp smem (in float4): input ring + spike accumulator
#define IN_F4   (NBUF * RPW * PITCH)     // 576
#define ACC_F4  (RPW * ACC_PITCH)        // 1056
#define WARP_F4 (IN_F4 + ACC_F4)         // 1632
#define SMEM_BYTES (WARPS * WARP_F4 * 16)  // 104448

__device__ __forceinline__ void cp16(uint32_t dst_smem, const float4* src) {
    asm volatile("cp.async.cg.shared.global [%0], [%1], 16;\n"
                 :: "r"(dst_smem), "l"(src));
}
__device__ __forceinline__ void cp_commit() {
    asm volatile("cp.async.commit_group;\n");
}
__device__ __forceinline__ void cp_wait1() {
    asm volatile("cp.async.wait_group 1;\n");
}
__device__ __forceinline__ void stwt(float4* p, float4 v) {
    asm volatile("st.global.wt.v4.f32 [%0], {%1, %2, %3, %4};\n"
                 :: "l"(p), "f"(v.x), "f"(v.y), "f"(v.z), "f"(v.w)
                 : "memory");
}

__global__ void __launch_bounds__(NT, 2)
lif_kernel(const float* __restrict__ x,
           const float* __restrict__ beta_p,
           const float* __restrict__ vth_p,
           float* __restrict__ out)
{
    extern __shared__ float4 smem[];

    const int tid  = threadIdx.x;
    const int w    = tid >> 5;                    // warp id -> SMSP w
    const int lane = tid & 31;
    const int r0   = blockIdx.x * NT + w * RPW;   // first row of this warp

    float4* win  = smem + w * WARP_F4;            // input ring [NBUF][RPW*PITCH]
    float4* wacc = win + IN_F4;                   // accumulator [RPW*ACC_PITCH]
    const uint32_t win_s = (uint32_t)__cvta_generic_to_shared(win);

    const float beta = __ldg(beta_p);
    const float vth  = __ldg(vth_p + ((r0 + lane) & (Cdim - 1)));

    const float4* __restrict__ xg = (const float4*)x;
    float4* __restrict__ og = (float4*)out;
    const int row_f4 = Tdim / 4;                  // 256 float4 per global row

    // ---- prologue: preload tiles 0..1 into the warp's ring ----
    #pragma unroll
    for (int p = 0; p < NBUF; ++p) {
        const int tcol0 = p * F4;
        #pragma unroll
        for (int i = 0; i < F4; ++i) {
            int idx = i * 32 + lane;
            int row = idx >> 3;                   // idx / F4
            int col = idx & 7;                    // idx % F4
            cp16(win_s + (uint32_t)(p * RPW * PITCH + row * PITCH + col) * 16u,
                 xg + (size_t)(r0 + row) * row_f4 + tcol0 + col);
        }
        cp_commit();
    }

    float mem = 0.0f;
    float rst = 0.0f;
    int b = 0;

    for (int it = 0; it < NTILES; ++it) {
        cp_wait1();                               // tile `it` landed
        __syncwarp();                             // cross-lane visibility

        // ---- recurrence: lane owns row, 32 steps; spikes -> acc slice ----
        float4* mybuf = win + b * RPW * PITCH + lane * PITCH;
        float4* myacc = wacc + lane * ACC_PITCH + (it & (GROUP - 1)) * F4;
        #pragma unroll
        for (int c = 0; c < F4; ++c) {
            float4 v = mybuf[c];
            float4 s;
            #define LIF_STEP(XV, SV)                                   \
                do {                                                   \
                    float t1 = __fmul_rn(mem, beta);                   \
                    float t2 = __fadd_rn(t1, (XV));                    \
                    mem = __fadd_rn(t2, -rst);                         \
                    float spk = (mem > vth) ? 1.0f : 0.0f;             \
                    (SV) = spk;                                        \
                    rst = (mem > vth) ? vth : 0.0f;                    \
                } while (0)
            LIF_STEP(v.x, s.x);
            LIF_STEP(v.y, s.y);
            LIF_STEP(v.z, s.z);
            LIF_STEP(v.w, s.w);
            #undef LIF_STEP
            myacc[c] = s;
        }
        __syncwarp();     // acc visible cross-lane; input buf fully consumed

        // ---- every GROUP tiles: 512B/row write-through bursts ----
        if ((it & (GROUP - 1)) == (GROUP - 1)) {
            const int tbase = (it - (GROUP - 1)) * F4;
            #pragma unroll
            for (int i = 0; i < RPW; ++i) {
                stwt(og + (size_t)(r0 + i) * row_f4 + tbase + lane,
                     wacc[i * ACC_PITCH + lane]);
            }
        }

        // ---- refill buf b with tile it+2; always commit a group ----
        const int ip = it + NBUF;
        if (ip < NTILES) {
            const int tcol0 = ip * F4;
            #pragma unroll
            for (int i = 0; i < F4; ++i) {
                int idx = i * 32 + lane;
                int row = idx >> 3;
                int col = idx & 7;
                cp16(win_s + (uint32_t)(b * RPW * PITCH + row * PITCH + col) * 16u,
                     xg + (size_t)(r0 + row) * row_f4 + tcol0 + col);
            }
        }
        cp_commit();

        b ^= 1;
    }
}

extern "C" void kernel_launch(void* const* d_in, const int* in_sizes, int n_in,
                              void* d_out, int out_size)
{
    const float* x    = (const float*)d_in[0];  // (128, 512, 1024) fp32
    const float* beta = (const float*)d_in[1];  // scalar fp32
    const float* vth  = (const float*)d_in[2];  // (512,) fp32
    float* out        = (float*)d_out;          // (128, 512, 1024) fp32

    cudaFuncSetAttribute(lif_kernel,
                         cudaFuncAttributeMaxDynamicSharedMemorySize,
                         SMEM_BYTES);
    lif_kernel<<<(Bdim * Cdim) / NT, NT, SMEM_BYTES>>>(x, beta, vth, out);
}

// round 12
// speedup vs baseline: 1.0995x; 1.0995x over previous
#include <cuda_runtime.h>
#include <cstdint>

// Spiking1DLIFLayer: B=128, C=512, T=1024  (row=(b,c), serial recurrence over T)
//   mem = (mem*beta + x[t]) - spk_prev*Vth[c] ;  spk = mem > Vth[c]
// Pure HBM-bound stream (256MB in + 256MB out).
//
// R12: R10 (winner: wt stores + 512B write batching, 92.3us timed) with the
// single measured lever pushed further: GROUP 4 -> 8, i.e. 1KB-contiguous
// write-through bursts per row. Burst-size trend: 128B->99.1us, 512B->85.6us
// in-kernel. Cost: 47.1KB smem/block -> 4 blocks/SM (32KB reads in flight,
// still above the ~25KB latency-hiding floor). R11 proved SMSP spreading is
// NOT needed (dependent-chain warps undersubscribe the issue port), so the
// 1-warp-block structure stays. Numerics bit-identical (rel_err 0.0 R1-R11).

#define Bdim 128
#define Cdim 512
#define Tdim 1024
#define NT    32                 // threads per block == rows per block (1 warp)
#define TS    32                 // time-tile (floats)
#define F4    (TS / 4)           // 8 float4 per row per tile
#define PITCH (F4 + 1)           // 9 -> conflict-free input-buf access
#define NBUF  3
#define NTILES (Tdim / TS)       // 32
#define GROUP 8                  // tiles per write burst (8*128B = 1KB/row)
#define ACC_F4 (GROUP * F4)      // 64 float4 per row in accumulator
#define ACC_PITCH (ACC_F4 + 1)   // 65

__device__ __forceinline__ void cp16(uint32_t dst_smem, const float4* src) {
    asm volatile("cp.async.cg.shared.global [%0], [%1], 16;\n"
                 :: "r"(dst_smem), "l"(src));
}
__device__ __forceinline__ void cp_commit() {
    asm volatile("cp.async.commit_group;\n");
}
__device__ __forceinline__ void cp_wait2() {
    asm volatile("cp.async.wait_group 2;\n");
}
__device__ __forceinline__ void stwt(float4* p, float4 v) {
    asm volatile("st.global.wt.v4.f32 [%0], {%1, %2, %3, %4};\n"
                 :: "l"(p), "f"(v.x), "f"(v.y), "f"(v.z), "f"(v.w)
                 : "memory");
}

__global__ void __launch_bounds__(NT, 4)
lif_kernel(const float* __restrict__ x,
           const float* __restrict__ beta_p,
           const float* __restrict__ vth_p,
           float* __restrict__ out)
{
    __shared__ float4 tile[NBUF][NT * PITCH];      // input staging (13.8 KB)
    __shared__ float4 acc[NT * ACC_PITCH];         // spike accumulator (33.3 KB)

    const int tid = threadIdx.x;
    const int r0  = blockIdx.x * NT;
    const float beta = __ldg(beta_p);
    const float vth  = __ldg(vth_p + ((r0 + tid) & (Cdim - 1)));

    const float4* __restrict__ xg = (const float4*)x;
    float4* __restrict__ og = (float4*)out;
    const int row_f4 = Tdim / 4;                  // 256 float4 per global row

    // ---- prologue: preload tiles 0..2 ----
    #pragma unroll
    for (int p = 0; p < NBUF; ++p) {
        const int tcol0 = p * F4;
        uint32_t sbase = (uint32_t)__cvta_generic_to_shared(&tile[p][0]);
        #pragma unroll
        for (int i = 0; i < F4; ++i) {
            int idx = i * NT + tid;
            int row = idx >> 3;                   // idx / F4
            int col = idx & 7;                    // idx % F4
            cp16(sbase + (uint32_t)(row * PITCH + col) * 16u,
                 xg + (size_t)(r0 + row) * row_f4 + tcol0 + col);
        }
        cp_commit();
    }

    float mem = 0.0f;
    float rst = 0.0f;
    int b = 0;

    for (int it = 0; it < NTILES; ++it) {
        cp_wait2();                               // tile `it` landed
        __syncthreads();                          // nw=1: cheap; async->CTA vis

        // ---- recurrence: thread owns row `tid`, 32 steps ----
        // spikes go to the accumulator slice for this tile within the group
        float4* mybuf = &tile[b][tid * PITCH];
        float4* myacc = &acc[tid * ACC_PITCH + (it & (GROUP - 1)) * F4];
        #pragma unroll
        for (int c = 0; c < F4; ++c) {
            float4 v = mybuf[c];
            float4 s;
            #define LIF_STEP(XV, SV)                                   \
                do {                                                   \
                    float t1 = __fmul_rn(mem, beta);                   \
                    float t2 = __fadd_rn(t1, (XV));                    \
                    mem = __fadd_rn(t2, -rst);                         \
                    float spk = (mem > vth) ? 1.0f : 0.0f;             \
                    (SV) = spk;                                        \
                    rst = (mem > vth) ? vth : 0.0f;                    \
                } while (0)
            LIF_STEP(v.x, s.x);
            LIF_STEP(v.y, s.y);
            LIF_STEP(v.z, s.z);
            LIF_STEP(v.w, s.w);
            #undef LIF_STEP
            myacc[c] = s;
        }
        __syncthreads();   // input-buf reads done (before refill) + acc visible

        // ---- every GROUP tiles: flush 1KB/row write-through bursts ----
        if ((it & (GROUP - 1)) == (GROUP - 1)) {
            const int tbase = (it - (GROUP - 1)) * F4;   // first f4 col of group
            #pragma unroll
            for (int i = 0; i < NT; ++i) {
                // two warp-instructions per row: lanes cover 64 consecutive f4
                stwt(og + (size_t)(r0 + i) * row_f4 + tbase + tid,
                     acc[i * ACC_PITCH + tid]);
                stwt(og + (size_t)(r0 + i) * row_f4 + tbase + 32 + tid,
                     acc[i * ACC_PITCH + 32 + tid]);
            }
        }

        // ---- refill buf b with tile it+3; always commit a group ----
        const int ip = it + NBUF;
        if (ip < NTILES) {
            const int tcol0 = ip * F4;
            uint32_t sbase = (uint32_t)__cvta_generic_to_shared(&tile[b][0]);
            #pragma unroll
            for (int i = 0; i < F4; ++i) {
                int idx = i * NT + tid;
                int row = idx >> 3;
                int col = idx & 7;
                cp16(sbase + (uint32_t)(row * PITCH + col) * 16u,
                     xg + (size_t)(r0 + row) * row_f4 + tcol0 + col);
            }
        }
        cp_commit();

        b = (b == NBUF - 1) ? 0 : b + 1;
    }
}

extern "C" void kernel_launch(void* const* d_in, const int* in_sizes, int n_in,
                              void* d_out, int out_size)
{
    const float* x    = (const float*)d_in[0];  // (128, 512, 1024) fp32
    const float* beta = (const float*)d_in[1];  // scalar fp32
    const float* vth  = (const float*)d_in[2];  // (512,) fp32
    float* out        = (float*)d_out;          // (128, 512, 1024) fp32

    lif_kernel<<<(Bdim * Cdim) / NT, NT>>>(x, beta, vth, out);
}

// round 13
// speedup vs baseline: 1.1832x; 1.0761x over previous
#include <cuda_runtime.h>
#include <cstdint>

// Spiking1DLIFLayer: B=128, C=512, T=1024  (row=(b,c), serial recurrence over T)
//   mem = (mem*beta + x[t]) - spk_prev*Vth[c] ;  spk = mem > Vth[c]
// Pure HBM-bound stream (256MB in + 256MB out).
//
// R13: BIT-PACKED spike accumulator. R10 (512B wt bursts, 7 blk/SM) = 92.3us;
// R12 (1KB bursts via 33KB fp32 acc) tanked occupancy (4 blk/SM) -> 108us.
// Spikes are 1-bit: pack 32 timesteps/thread/tile into one uint32 built in
// registers (predicate shift-or, bit-exact), 4B STS per tile. GROUP=8 acc =
// 1.2KB instead of 33KB -> ~15KB smem total, ~13 blk/SM, AND 1KB-contiguous
// write-through bursts (flush expands nibbles->float4). wt keeps L2 clean at
// exit (no ~15us replay-boundary dirty-drain tax, established R2-R9).
// Numerics bit-identical to reference (rel_err 0.0 in R1-R12).

#define Bdim 128
#define Cdim 512
#define Tdim 1024
#define NT    32                 // threads per block == rows per block (1 warp)
#define TS    32                 // time-tile (floats) == bits per mask
#define F4    (TS / 4)           // 8 float4 per row per tile
#define PITCH (F4 + 1)           // 9 -> conflict-free input-buf access
#define NBUF  3
#define NTILES (Tdim / TS)       // 32
#define GROUP 8                  // tiles per write burst (8*128B = 1KB/row)
#define BPITCH (GROUP + 1)       // 9 words/row -> conflict-free STS stride

__device__ __forceinline__ void cp16(uint32_t dst_smem, const float4* src) {
    asm volatile("cp.async.cg.shared.global [%0], [%1], 16;\n"
                 :: "r"(dst_smem), "l"(src));
}
__device__ __forceinline__ void cp_commit() {
    asm volatile("cp.async.commit_group;\n");
}
__device__ __forceinline__ void cp_wait2() {
    asm volatile("cp.async.wait_group 2;\n");
}
__device__ __forceinline__ void stwt(float4* p, float4 v) {
    asm volatile("st.global.wt.v4.f32 [%0], {%1, %2, %3, %4};\n"
                 :: "l"(p), "f"(v.x), "f"(v.y), "f"(v.z), "f"(v.w)
                 : "memory");
}
__device__ __forceinline__ float4 nib2f4(uint32_t word, int off) {
    float4 s;
    s.x = ((word >> (off + 0)) & 1u) ? 1.0f : 0.0f;
    s.y = ((word >> (off + 1)) & 1u) ? 1.0f : 0.0f;
    s.z = ((word >> (off + 2)) & 1u) ? 1.0f : 0.0f;
    s.w = ((word >> (off + 3)) & 1u) ? 1.0f : 0.0f;
    return s;
}

__global__ void __launch_bounds__(NT, 8)
lif_kernel(const float* __restrict__ x,
           const float* __restrict__ beta_p,
           const float* __restrict__ vth_p,
           float* __restrict__ out)
{
    __shared__ float4   tile[NBUF][NT * PITCH];    // input staging (13.8 KB)
    __shared__ uint32_t bits[NT * BPITCH];         // packed spikes (1.2 KB)

    const int tid = threadIdx.x;
    const int r0  = blockIdx.x * NT;
    const float beta = __ldg(beta_p);
    const float vth  = __ldg(vth_p + ((r0 + tid) & (Cdim - 1)));

    const float4* __restrict__ xg = (const float4*)x;
    float4* __restrict__ og = (float4*)out;
    const int row_f4 = Tdim / 4;                  // 256 float4 per global row

    // ---- prologue: preload tiles 0..2 ----
    #pragma unroll
    for (int p = 0; p < NBUF; ++p) {
        const int tcol0 = p * F4;
        uint32_t sbase = (uint32_t)__cvta_generic_to_shared(&tile[p][0]);
        #pragma unroll
        for (int i = 0; i < F4; ++i) {
            int idx = i * NT + tid;
            int row = idx >> 3;                   // idx / F4
            int col = idx & 7;                    // idx % F4
            cp16(sbase + (uint32_t)(row * PITCH + col) * 16u,
                 xg + (size_t)(r0 + row) * row_f4 + tcol0 + col);
        }
        cp_commit();
    }

    float mem = 0.0f;
    float rst = 0.0f;
    int b = 0;

    for (int it = 0; it < NTILES; ++it) {
        cp_wait2();                               // tile `it` landed
        __syncthreads();                          // nw=1: cheap; async->CTA vis

        // ---- recurrence: thread owns row `tid`, 32 steps -> 32-bit mask ----
        float4* mybuf = &tile[b][tid * PITCH];
        uint32_t mask = 0u;
        #pragma unroll
        for (int c = 0; c < F4; ++c) {
            float4 v = mybuf[c];
            #define LIF_STEP(XV, BIT)                                  \
                do {                                                   \
                    float t1 = __fmul_rn(mem, beta);                   \
                    float t2 = __fadd_rn(t1, (XV));                    \
                    mem = __fadd_rn(t2, -rst);                         \
                    bool p = (mem > vth);                              \
                    mask |= (p ? 1u : 0u) << (BIT);                    \
                    rst = p ? vth : 0.0f;                              \
                } while (0)
            LIF_STEP(v.x, c * 4 + 0);
            LIF_STEP(v.y, c * 4 + 1);
            LIF_STEP(v.z, c * 4 + 2);
            LIF_STEP(v.w, c * 4 + 3);
            #undef LIF_STEP
        }
        bits[tid * BPITCH + (it & (GROUP - 1))] = mask;   // 4B STS, no conflict
        __syncthreads();   // input-buf reads done (before refill) + bits visible

        // ---- every GROUP tiles: flush 1KB/row write-through bursts ----
        if ((it & (GROUP - 1)) == (GROUP - 1)) {
            const int tbase = (it - (GROUP - 1)) * F4;   // first f4 col of group
            const int w0  = tid >> 3;                    // word for 1st stwt
            const int off = (tid & 7) * 4;               // nibble offset
            #pragma unroll
            for (int i = 0; i < NT; ++i) {
                // lanes cover 64 consecutive f4 = 1KB contiguous per row
                uint32_t wa = bits[i * BPITCH + w0];         // 8-lane broadcast
                uint32_t wb = bits[i * BPITCH + 4 + w0];
                stwt(og + (size_t)(r0 + i) * row_f4 + tbase + tid,
                     nib2f4(wa, off));
                stwt(og + (size_t)(r0 + i) * row_f4 + tbase + 32 + tid,
                     nib2f4(wb, off));
            }
        }

        // ---- refill buf b with tile it+3; always commit a group ----
        const int ip = it + NBUF;
        if (ip < NTILES) {
            const int tcol0 = ip * F4;
            uint32_t sbase = (uint32_t)__cvta_generic_to_shared(&tile[b][0]);
            #pragma unroll
            for (int i = 0; i < F4; ++i) {
                int idx = i * NT + tid;
                int row = idx >> 3;
                int col = idx & 7;
                cp16(sbase + (uint32_t)(row * PITCH + col) * 16u,
                     xg + (size_t)(r0 + row) * row_f4 + tcol0 + col);
            }
        }
        cp_commit();

        b = (b == NBUF - 1) ? 0 : b + 1;
    }
}

extern "C" void kernel_launch(void* const* d_in, const int* in_sizes, int n_in,
                              void* d_out, int out_size)
{
    const float* x    = (const float*)d_in[0];  // (128, 512, 1024) fp32
    const float* beta = (const float*)d_in[1];  // scalar fp32
    const float* vth  = (const float*)d_in[2];  // (512,) fp32
    float* out        = (float*)d_out;          // (128, 512, 1024) fp32

    lif_kernel<<<(Bdim * Cdim) / NT, NT>>>(x, beta, vth, out);
}